// round 13
// baseline (speedup 1.0000x reference)
#include <cuda_runtime.h>
#include <cstdint>

#define NT 4096
#define DM 1024

// Scratch (static __device__ globals — allocation-free per harness rules)
__device__ float g_q[(size_t)NT * DM];
__device__ float g_k[(size_t)NT * DM];
__device__ float g_v[(size_t)NT * DM];
__device__ float g_s[(size_t)NT * NT];
__device__ float g_xr[(size_t)NT * DM];    // tf32-rounded x
__device__ float g_wqr[(size_t)DM * DM];   // tf32-rounded weights
__device__ float g_wkr[(size_t)DM * DM];
__device__ float g_wvr[(size_t)DM * DM];

__device__ __forceinline__ uint32_t f2tf32(float x)
{
    uint32_t y;
    asm("cvt.rna.tf32.f32 %0, %1;" : "=r"(y) : "f"(x));
    return y;
}
__device__ __forceinline__ float f2tf32f(float x)
{
    return __uint_as_float(f2tf32(x));
}

__device__ __forceinline__ void mma_tf32(float c[4], uint32_t a0, uint32_t a1,
                                         uint32_t a2, uint32_t a3,
                                         uint32_t b0, uint32_t b1)
{
    asm volatile(
        "mma.sync.aligned.m16n8k8.row.col.f32.tf32.tf32.f32 "
        "{%0,%1,%2,%3}, {%4,%5,%6,%7}, {%8,%9}, {%0,%1,%2,%3};"
        : "+f"(c[0]), "+f"(c[1]), "+f"(c[2]), "+f"(c[3])
        : "r"(a0), "r"(a1), "r"(a2), "r"(a3), "r"(b0), "r"(b1));
}

// ldmatrix x4 on 32-bit data: thread t receives element (t/4, t%4) of the
// 8x4 b32 tile whose 8 row addresses are supplied by threads 8m..8m+7.
__device__ __forceinline__ void ldsm_x4(uint32_t& d0, uint32_t& d1,
                                        uint32_t& d2, uint32_t& d3, uint32_t addr)
{
    asm volatile("ldmatrix.sync.aligned.m8n8.x4.shared.b16 {%0,%1,%2,%3}, [%4];"
                 : "=r"(d0), "=r"(d1), "=r"(d2), "=r"(d3) : "r"(addr));
}

__device__ __forceinline__ void cp_async16(uint32_t dst_smem, const void* src)
{
    asm volatile("cp.async.cg.shared.global [%0], [%1], 16;\n"
                 :: "r"(dst_smem), "l"(src));
}
__device__ __forceinline__ void cp_commit()
{
    asm volatile("cp.async.commit_group;\n" ::: "memory");
}
__device__ __forceinline__ void cp_wait1()
{
    asm volatile("cp.async.wait_group 1;\n" ::: "memory");
}

// ---------------------------------------------------------------------------
// Elementwise tf32 pre-round (float4 vectorized)
// ---------------------------------------------------------------------------
__global__ __launch_bounds__(256)
void round_kernel(const float4* __restrict__ in, float4* __restrict__ out, int n4)
{
    int i = blockIdx.x * blockDim.x + threadIdx.x;
    if (i < n4) {
        float4 v = in[i];
        out[i] = make_float4(f2tf32f(v.x), f2tf32f(v.y), f2tf32f(v.z), f2tf32f(v.w));
    }
}

// ---------------------------------------------------------------------------
// tf32 MMA GEMM NT. CTA tile 128x128, 8 warps of 64x32 (2m x 4n), BK=32,
// 3-stage cp.async pipeline, one barrier/iter, 2 CTA/SM (16 warps).
// Fragments via ldmatrix.x4 for BOTH operands.
// C[M,N] = A[M,K] * B[N,K]^T, operands pre-rounded to tf32.
// blockIdx.z selects (B, C) pair. CAUSAL: skip blocks above diagonal.
// ROUND_OUT: tf32-round output.
// ---------------------------------------------------------------------------
template<bool CAUSAL, bool ROUND_OUT>
__global__ __launch_bounds__(256, 2)
void mma_nt_kernel(const float* __restrict__ A,
                   const float* __restrict__ B0, const float* __restrict__ B1,
                   float* __restrict__ C0, float* __restrict__ C1,
                   int M, int Ncols, int K)
{
    constexpr int BM = 128, BK = 32;
    constexpr int STR = BK + 4;                 // 36 floats = 9 16B-units; 9%8=1
    constexpr int TSZ = BM * STR;               // 4608 floats per operand
    constexpr int TS = 2 * TSZ;                 // 36864 B per stage

    extern __shared__ float sm[];               // [3][TS]

    const int bx = blockIdx.x, by = blockIdx.y, bz = blockIdx.z;
    if (CAUSAL && bx > by) return;

    const float* __restrict__ B = (bz == 0) ? B0 : B1;
    float* __restrict__ C       = (bz == 0) ? C0 : C1;

    const int m0 = by * BM, n0 = bx * BM;
    const int t    = threadIdx.x;
    const int lane = t & 31, warp = t >> 5;
    const int wm = warp & 1, wn = warp >> 1;    // 2m x 4n, 64x32 each
    const int gID = lane >> 2, tig = lane & 3;

    const uint32_t thrA = (uint32_t)(((wm * 64 + ((lane >> 3) & 1) * 8 + (lane & 7)) * STR
                                      + ((lane >> 4) & 1) * 4) * 4);
    const uint32_t thrB = (uint32_t)(((wn * 32 + ((lane >> 4) & 1) * 8 + (lane & 7)) * STR
                                      + ((lane >> 3) & 1) * 4) * 4);

    const float* Ap = A + (size_t)m0 * K;
    const float* Bp = B + (size_t)n0 * K;
    const uint32_t sbase = (uint32_t)__cvta_generic_to_shared(sm);

    float c[4][4][4];
#pragma unroll
    for (int i = 0; i < 4; i++)
#pragma unroll
        for (int j = 0; j < 4; j++)
#pragma unroll
            for (int r = 0; r < 4; r++) c[i][j][r] = 0.f;

    auto issue = [&](int k0, int stg) {
        const uint32_t base = sbase + (uint32_t)(stg * TS) * 4u;
#pragma unroll
        for (int l = t; l < 1024; l += 256) {
            const int r  = l >> 3;
            const int cg = l & 7;
            cp_async16(base + (uint32_t)((r * STR + cg * 4) * 4),
                       Ap + (size_t)r * K + k0 + cg * 4);
            cp_async16(base + (uint32_t)((TSZ + r * STR + cg * 4) * 4),
                       Bp + (size_t)r * K + k0 + cg * 4);
        }
    };

    const int nk = K / BK;

    issue(0, 0);       cp_commit();
    issue(BK, 1);      cp_commit();

    for (int i = 0; i < nk; i++) {
        const int stg = i % 3;
        cp_wait1();
        __syncthreads();                 // readers of slot (i-1)%3 retired
        if (i + 2 < nk)
            issue((i + 2) * BK, (i + 2) % 3);   // writes slot (i-1)%3
        cp_commit();                     // uniform group numbering

        const uint32_t baseA = sbase + (uint32_t)(stg * TS) * 4u;
        const uint32_t baseB = baseA + (uint32_t)TSZ * 4u;
#pragma unroll
        for (int ks = 0; ks < 4; ks++) {
            const int kr = ks * 8;
            uint32_t a[4][4], b[4][2];
#pragma unroll
            for (int mt = 0; mt < 4; mt++)
                ldsm_x4(a[mt][0], a[mt][1], a[mt][2], a[mt][3],
                        baseA + thrA + (uint32_t)((mt * 16 * STR + kr) * 4));
#pragma unroll
            for (int p = 0; p < 2; p++)
                ldsm_x4(b[2 * p][0], b[2 * p][1], b[2 * p + 1][0], b[2 * p + 1][1],
                        baseB + thrB + (uint32_t)((p * 16 * STR + kr) * 4));
#pragma unroll
            for (int mt = 0; mt < 4; mt++)
#pragma unroll
                for (int nt = 0; nt < 4; nt++)
                    mma_tf32(c[mt][nt], a[mt][0], a[mt][1], a[mt][2], a[mt][3],
                             b[nt][0], b[nt][1]);
        }
    }

#pragma unroll
    for (int mt = 0; mt < 4; mt++) {
        const int row = m0 + wm * 64 + mt * 16 + gID;
#pragma unroll
        for (int nt = 0; nt < 4; nt++) {
            const int col = n0 + wn * 32 + nt * 8 + tig * 2;
            float o0 = ROUND_OUT ? f2tf32f(c[mt][nt][0]) : c[mt][nt][0];
            float o1 = ROUND_OUT ? f2tf32f(c[mt][nt][1]) : c[mt][nt][1];
            float o2 = ROUND_OUT ? f2tf32f(c[mt][nt][2]) : c[mt][nt][2];
            float o3 = ROUND_OUT ? f2tf32f(c[mt][nt][3]) : c[mt][nt][3];
            *reinterpret_cast<float2*>(C + (size_t)row * Ncols + col) = make_float2(o0, o1);
            *reinterpret_cast<float2*>(C + (size_t)(row + 8) * Ncols + col) = make_float2(o2, o3);
        }
    }
}

// ---------------------------------------------------------------------------
// tf32 MMA GEMM NN with causal k-limit, 3-stage cp.async pipeline, one barrier.
// C[M,N] = A[M,K] * B[K,N], k < m0+BM. 128x128 tile, 2 CTA/SM.
// A frags via ldmatrix; B frags scalar (transposed pattern, .trans b16-only).
// ---------------------------------------------------------------------------
__global__ __launch_bounds__(256, 2)
void mma_nn_causal_kernel(const float* __restrict__ A, const float* __restrict__ B,
                          float* __restrict__ C, int M, int Ncols, int K)
{
    constexpr int BM = 128, BN = 128, BK = 32;
    constexpr int STRA = BK + 4;                 // 36
    constexpr int STRB = BN + 8;                 // 136
    constexpr int TA = BM * STRA;                // 4608
    constexpr int TB = BK * STRB;                // 4352
    constexpr int TS = TA + TB;

    extern __shared__ float sm[];                // [3][TS]

    const int bx = blockIdx.x, by = blockIdx.y;
    const int m0 = by * BM, n0 = bx * BN;
    const int t    = threadIdx.x;
    const int lane = t & 31, warp = t >> 5;
    const int wm = warp & 1, wn = warp >> 1;
    const int gID = lane >> 2, tig = lane & 3;

    const uint32_t thrA = (uint32_t)(((wm * 64 + ((lane >> 3) & 1) * 8 + (lane & 7)) * STRA
                                      + ((lane >> 4) & 1) * 4) * 4);

    const float* Ap = A + (size_t)m0 * K;
    const uint32_t sbase = (uint32_t)__cvta_generic_to_shared(sm);

    float c[4][4][4];
#pragma unroll
    for (int i = 0; i < 4; i++)
#pragma unroll
        for (int j = 0; j < 4; j++)
#pragma unroll
            for (int r = 0; r < 4; r++) c[i][j][r] = 0.f;

    auto issue = [&](int k0, int stg) {
        const uint32_t base = sbase + (uint32_t)(stg * TS) * 4u;
#pragma unroll
        for (int l = t; l < 1024; l += 256) {
            {
                const int r  = l >> 3;
                const int cg = l & 7;
                cp_async16(base + (uint32_t)((r * STRA + cg * 4) * 4),
                           Ap + (size_t)r * K + k0 + cg * 4);
            }
            {
                const int kk = l >> 5;
                const int ng = l & 31;
                cp_async16(base + (uint32_t)((TA + kk * STRB + ng * 4) * 4),
                           B + (size_t)(k0 + kk) * Ncols + n0 + ng * 4);
            }
        }
    };

    const int kmax = min(K, m0 + BM);
    const int nk = kmax / BK;                    // >= 4 always

    issue(0, 0);   cp_commit();
    issue(BK, 1);  cp_commit();

    for (int i = 0; i < nk; i++) {
        const int stg = i % 3;
        cp_wait1();
        __syncthreads();
        if (i + 2 < nk)
            issue((i + 2) * BK, (i + 2) % 3);
        cp_commit();

        const uint32_t baseA = sbase + (uint32_t)(stg * TS) * 4u;
        const uint32_t* B0 = reinterpret_cast<const uint32_t*>(sm + stg * TS) + TA;
#pragma unroll
        for (int ks = 0; ks < 4; ks++) {
            const int kr = ks * 8;
            uint32_t a[4][4], b[4][2];
#pragma unroll
            for (int mt = 0; mt < 4; mt++)
                ldsm_x4(a[mt][0], a[mt][1], a[mt][2], a[mt][3],
                        baseA + thrA + (uint32_t)((mt * 16 * STRA + kr) * 4));
#pragma unroll
            for (int nt = 0; nt < 4; nt++) {
                const int c0 = wn * 32 + nt * 8 + gID;
                b[nt][0] = B0[(kr + tig) * STRB + c0];
                b[nt][1] = B0[(kr + tig + 4) * STRB + c0];
            }
#pragma unroll
            for (int mt = 0; mt < 4; mt++)
#pragma unroll
                for (int nt = 0; nt < 4; nt++)
                    mma_tf32(c[mt][nt], a[mt][0], a[mt][1], a[mt][2], a[mt][3],
                             b[nt][0], b[nt][1]);
        }
    }

#pragma unroll
    for (int mt = 0; mt < 4; mt++) {
        const int row = m0 + wm * 64 + mt * 16 + gID;
#pragma unroll
        for (int nt = 0; nt < 4; nt++) {
            const int col = n0 + wn * 32 + nt * 8 + tig * 2;
            *reinterpret_cast<float2*>(C + (size_t)row * Ncols + col) =
                make_float2(c[mt][nt][0], c[mt][nt][1]);
            *reinterpret_cast<float2*>(C + (size_t)(row + 8) * Ncols + col) =
                make_float2(c[mt][nt][2], c[mt][nt][3]);
        }
    }
}

// ---------------------------------------------------------------------------
// Exact JAX *partitionable* threefry2x32 uniform (key = (0, 42)).
// ---------------------------------------------------------------------------
__device__ __forceinline__ float jax_uniform(uint32_t idx)
{
    const uint32_t k0 = 0u, k1 = 42u;
    const uint32_t k2 = 0x1BD11BDAu ^ k0 ^ k1;

    uint32_t x0 = 0u  + k0;
    uint32_t x1 = idx + k1;

#define TF_ROUND(r) { x0 += x1; x1 = __funnelshift_l(x1, x1, (r)); x1 ^= x0; }
    TF_ROUND(13) TF_ROUND(15) TF_ROUND(26) TF_ROUND(6)
    x0 += k1; x1 += k2 + 1u;
    TF_ROUND(17) TF_ROUND(29) TF_ROUND(16) TF_ROUND(24)
    x0 += k2; x1 += k0 + 2u;
    TF_ROUND(13) TF_ROUND(15) TF_ROUND(26) TF_ROUND(6)
    x0 += k0; x1 += k1 + 3u;
    TF_ROUND(17) TF_ROUND(29) TF_ROUND(16) TF_ROUND(24)
    x0 += k1; x1 += k2 + 4u;
    TF_ROUND(13) TF_ROUND(15) TF_ROUND(26) TF_ROUND(6)
    x0 += k2; x1 += k0 + 5u;
#undef TF_ROUND

    uint32_t bits = x0 ^ x1;
    return __uint_as_float((bits >> 9) | 0x3f800000u) - 1.0f;
}

// ---------------------------------------------------------------------------
// Single-pass register-resident softmax (causal, /32) + JAX dropout.
// Writes tf32-rounded weights; zero-fills to round_up(len,128).
// ---------------------------------------------------------------------------
__global__ __launch_bounds__(256)
void softmax_dropout_kernel(float* __restrict__ S)
{
    const int i = blockIdx.x;
    const int t = threadIdx.x;
    const int len = i + 1;
    const int wlimit = (len + 127) & ~127;
    float* row = S + (size_t)i * NT;

    const int warp = t >> 5, lane = t & 31;
    __shared__ float red_m[8], red_s[8];

    const float inv_scale = 0.03125f;  // 1/sqrt(1024)

    float vals[16];
    float lm = -INFINITY;
#pragma unroll
    for (int c = 0; c < 16; c++) {
        const int j = t + 256 * c;
        float x = (j < len) ? row[j] * inv_scale : -INFINITY;
        vals[c] = x;
        lm = fmaxf(lm, x);
    }
#pragma unroll
    for (int o = 16; o; o >>= 1) lm = fmaxf(lm, __shfl_xor_sync(~0u, lm, o));
    if (lane == 0) red_m[warp] = lm;
    __syncthreads();
    float m = red_m[0];
#pragma unroll
    for (int w = 1; w < 8; w++) m = fmaxf(m, red_m[w]);

    float ls = 0.f;
#pragma unroll
    for (int c = 0; c < 16; c++) {
        const int j = t + 256 * c;
        if (j < len) {
            float e = __expf(vals[c] - m);
            vals[c] = e;
            ls += e;
        }
    }
#pragma unroll
    for (int o = 16; o; o >>= 1) ls += __shfl_xor_sync(~0u, ls, o);
    if (lane == 0) red_s[warp] = ls;
    __syncthreads();
    float s = 0.f;
#pragma unroll
    for (int w = 0; w < 8; w++) s += red_s[w];

    const float keep_scale = (1.0f / 0.9f) / s;
    const uint32_t base = (uint32_t)i * (uint32_t)NT;
#pragma unroll
    for (int c = 0; c < 16; c++) {
        const int j = t + 256 * c;
        if (j < wlimit) {
            float w = 0.f;
            if (j < len) {
                float u = jax_uniform(base + (uint32_t)j);
                w = (u < 0.9f) ? f2tf32f(vals[c] * keep_scale) : 0.f;
            }
            row[j] = w;
        }
    }
}

// ---------------------------------------------------------------------------
extern "C" void kernel_launch(void* const* d_in, const int* in_sizes, int n_in,
                              void* d_out, int out_size)
{
    const float* x  = (const float*)d_in[0];
    const float* wq = (const float*)d_in[1];
    const float* wk = (const float*)d_in[2];
    const float* wv = (const float*)d_in[3];
    float* out = (float*)d_out;

    float *q, *k, *v, *s, *xr, *wqr, *wkr, *wvr;
    cudaGetSymbolAddress((void**)&q, g_q);
    cudaGetSymbolAddress((void**)&k, g_k);
    cudaGetSymbolAddress((void**)&v, g_v);
    cudaGetSymbolAddress((void**)&s, g_s);
    cudaGetSymbolAddress((void**)&xr, g_xr);
    cudaGetSymbolAddress((void**)&wqr, g_wqr);
    cudaGetSymbolAddress((void**)&wkr, g_wkr);
    cudaGetSymbolAddress((void**)&wvr, g_wvr);

    constexpr int sh_nt = 3 * 2 * (128 * 36) * 4;              // 110592 B
    constexpr int sh_nn = 3 * (128 * 36 + 32 * 136) * 4;       // 107520 B

    static bool init_done = false;
    static cudaStream_t s1;
    static cudaEvent_t e_x, e_v;
    if (!init_done) {
        cudaFuncSetAttribute(mma_nt_kernel<false, true>,
                             cudaFuncAttributeMaxDynamicSharedMemorySize, sh_nt);
        cudaFuncSetAttribute(mma_nt_kernel<true, false>,
                             cudaFuncAttributeMaxDynamicSharedMemorySize, sh_nt);
        cudaFuncSetAttribute(mma_nn_causal_kernel,
                             cudaFuncAttributeMaxDynamicSharedMemorySize, sh_nn);
        cudaStreamCreateWithFlags(&s1, cudaStreamNonBlocking);
        cudaEventCreateWithFlags(&e_x, cudaEventDisableTiming);
        cudaEventCreateWithFlags(&e_v, cudaEventDisableTiming);
        init_done = true;
    }

    dim3 blk(256);

    // main stream: round x, wq, wk
    round_kernel<<<(NT * DM / 4 + 255) / 256, blk>>>((const float4*)x,  (float4*)xr,  NT * DM / 4);
    cudaEventRecord(e_x, 0);
    round_kernel<<<(DM * DM / 4 + 255) / 256, blk>>>((const float4*)wq, (float4*)wqr, DM * DM / 4);
    round_kernel<<<(DM * DM / 4 + 255) / 256, blk>>>((const float4*)wk, (float4*)wkr, DM * DM / 4);

    // side stream: round wv, V projection (needs xr; joins before O-GEMM)
    cudaStreamWaitEvent(s1, e_x, 0);
    round_kernel<<<(DM * DM / 4 + 255) / 256, blk, 0, s1>>>((const float4*)wv, (float4*)wvr, DM * DM / 4);
    {
        dim3 grid_v(DM / 128, NT / 128, 1);
        mma_nt_kernel<false, true><<<grid_v, blk, sh_nt, s1>>>(
            xr, wvr, wvr, v, v, NT, DM, DM);
    }
    cudaEventRecord(e_v, s1);

    // main stream: QK projections fused via grid.z (outputs tf32-rounded)
    dim3 grid_qk(DM / 128, NT / 128, 2);
    mma_nt_kernel<false, true><<<grid_qk, blk, sh_nt>>>(
        xr, wqr, wkr, q, k, NT, DM, DM);

    // scores = Q @ K^T (skip blocks above diagonal; f32 output for softmax)
    dim3 grid_s(NT / 128, NT / 128, 1);
    mma_nt_kernel<true, false><<<grid_s, blk, sh_nt>>>(
        q, k, k, s, s, NT, NT, DM);

    // softmax + dropout (writes tf32-rounded weights, zero-fills to tile edge)
    softmax_dropout_kernel<<<NT, blk>>>(s);

    // join V before the O-GEMM
    cudaStreamWaitEvent(0, e_v, 0);

    // out = weights @ V (causal k-limit per row tile)
    dim3 grid_o(DM / 128, NT / 128);
    mma_nn_causal_kernel<<<grid_o, blk, sh_nn>>>(s, v, out, NT, DM, NT);
}

// round 15
// speedup vs baseline: 1.6028x; 1.6028x over previous
#include <cuda_runtime.h>
#include <cuda_fp16.h>
#include <cstdint>

#define NT 4096
#define DM 1024

// Scratch (static __device__ globals — allocation-free per harness rules)
__device__ __half g_q[(size_t)NT * DM];
__device__ __half g_k[(size_t)NT * DM];
__device__ __half g_v[(size_t)NT * DM];
__device__ float  g_s[(size_t)NT * NT];     // raw scores (f32)
__device__ __half g_w[(size_t)NT * NT];     // dropout-softmax weights (fp16)
__device__ __half g_xh[(size_t)NT * DM];    // fp16 x
__device__ __half g_wqh[(size_t)DM * DM];   // fp16 weights
__device__ __half g_wkh[(size_t)DM * DM];
__device__ __half g_wvh[(size_t)DM * DM];

// ---------------------------------------------------------------------------
// helpers
// ---------------------------------------------------------------------------
__device__ __forceinline__ void mma_f16(float c[4], uint32_t a0, uint32_t a1,
                                        uint32_t a2, uint32_t a3,
                                        uint32_t b0, uint32_t b1)
{
    asm volatile(
        "mma.sync.aligned.m16n8k16.row.col.f32.f16.f16.f32 "
        "{%0,%1,%2,%3}, {%4,%5,%6,%7}, {%8,%9}, {%0,%1,%2,%3};"
        : "+f"(c[0]), "+f"(c[1]), "+f"(c[2]), "+f"(c[3])
        : "r"(a0), "r"(a1), "r"(a2), "r"(a3), "r"(b0), "r"(b1));
}

__device__ __forceinline__ void ldsm_x4(uint32_t& d0, uint32_t& d1,
                                        uint32_t& d2, uint32_t& d3, uint32_t addr)
{
    asm volatile("ldmatrix.sync.aligned.m8n8.x4.shared.b16 {%0,%1,%2,%3}, [%4];"
                 : "=r"(d0), "=r"(d1), "=r"(d2), "=r"(d3) : "r"(addr));
}
__device__ __forceinline__ void ldsm_x4t(uint32_t& d0, uint32_t& d1,
                                         uint32_t& d2, uint32_t& d3, uint32_t addr)
{
    asm volatile("ldmatrix.sync.aligned.m8n8.x4.trans.shared.b16 {%0,%1,%2,%3}, [%4];"
                 : "=r"(d0), "=r"(d1), "=r"(d2), "=r"(d3) : "r"(addr));
}

__device__ __forceinline__ void cp_async16(uint32_t dst_smem, const void* src)
{
    asm volatile("cp.async.cg.shared.global [%0], [%1], 16;\n"
                 :: "r"(dst_smem), "l"(src));
}
__device__ __forceinline__ void cp_commit()
{
    asm volatile("cp.async.commit_group;\n" ::: "memory");
}
__device__ __forceinline__ void cp_wait1()
{
    asm volatile("cp.async.wait_group 1;\n" ::: "memory");
}

// ---------------------------------------------------------------------------
// Elementwise f32 -> fp16 convert (float4 -> 4 halves)
// ---------------------------------------------------------------------------
__global__ __launch_bounds__(256)
void tohalf_kernel(const float4* __restrict__ in, __half2* __restrict__ out, int n4)
{
    int i = blockIdx.x * blockDim.x + threadIdx.x;
    if (i < n4) {
        float4 v = in[i];
        out[2 * i]     = __floats2half2_rn(v.x, v.y);
        out[2 * i + 1] = __floats2half2_rn(v.z, v.w);
    }
}

// ---------------------------------------------------------------------------
// fp16 MMA GEMM NT. CTA tile 128x128, 8 warps of 64x32 (2m x 4n), BK=32,
// 3-stage cp.async pipeline, one barrier/iter, 2 CTA/SM.
// m16n8k16 f16 MMA, fp32 accumulate; fragments via ldmatrix.x4.
// C[M,N] = A[M,K] * B[N,K]^T (A, B fp16 k-major).
// blockIdx.z selects (B, C). CAUSAL: skip blocks above diagonal.
// HALF_OUT: store fp16 (QKV); else f32 (scores).
// ---------------------------------------------------------------------------
template<bool CAUSAL, bool HALF_OUT>
__global__ __launch_bounds__(256, 2)
void mma_nt_fp16(const __half* __restrict__ A,
                 const __half* __restrict__ B0, const __half* __restrict__ B1,
                 void* __restrict__ C0, void* __restrict__ C1,
                 int M, int Ncols, int K)
{
    constexpr int BM = 128, BK = 32;
    constexpr int STR = BK + 8;                 // 40 halves = 5 x 16B (odd): conflict-free
    constexpr int TSZ = BM * STR;               // 5120 halves per operand
    constexpr int TS = 2 * TSZ;                 // 20480 B per stage

    extern __shared__ __half smh[];             // [3][TS]

    const int bx = blockIdx.x, by = blockIdx.y, bz = blockIdx.z;
    if (CAUSAL && bx > by) return;

    const __half* __restrict__ B = (bz == 0) ? B0 : B1;
    void* __restrict__ C         = (bz == 0) ? C0 : C1;

    const int m0 = by * BM, n0 = bx * BM;
    const int t    = threadIdx.x;
    const int lane = t & 31, warp = t >> 5;
    const int wm = warp & 1, wn = warp >> 1;    // 2m x 4n, 64x32 each
    const int gID = lane >> 2, tig = lane & 3;

    // ldmatrix per-thread addresses (bytes):
    // A matrices {(m,k0),(m+8,k0),(m,k8),(m+8,k8)}; B {(n,k0),(n,k8),(n+8,k0),(n+8,k8)}
    const uint32_t thrA = (uint32_t)(((wm * 64 + ((lane >> 3) & 1) * 8 + (lane & 7)) * STR
                                      + ((lane >> 4) & 1) * 8) * 2);
    const uint32_t thrB = (uint32_t)(((wn * 32 + ((lane >> 4) & 1) * 8 + (lane & 7)) * STR
                                      + ((lane >> 3) & 1) * 8) * 2);

    const __half* Ap = A + (size_t)m0 * K;
    const __half* Bp = B + (size_t)n0 * K;
    const uint32_t sbase = (uint32_t)__cvta_generic_to_shared(smh);

    float c[4][4][4];
#pragma unroll
    for (int i = 0; i < 4; i++)
#pragma unroll
        for (int j = 0; j < 4; j++)
#pragma unroll
            for (int r = 0; r < 4; r++) c[i][j][r] = 0.f;

    auto issue = [&](int k0, int stg) {
        const uint32_t base = sbase + (uint32_t)(stg * TS) * 2u;
#pragma unroll
        for (int l = t; l < 512; l += 256) {    // A: 128 rows x 4 16B-chunks
            const int r  = l >> 2;
            const int cg = l & 3;
            cp_async16(base + (uint32_t)((r * STR + cg * 8) * 2),
                       Ap + (size_t)r * K + k0 + cg * 8);
        }
#pragma unroll
        for (int l = t; l < 512; l += 256) {    // B: 128 rows x 4 chunks
            const int r  = l >> 2;
            const int cg = l & 3;
            cp_async16(base + (uint32_t)((TSZ + r * STR + cg * 8) * 2),
                       Bp + (size_t)r * K + k0 + cg * 8);
        }
    };

    const int nk = K / BK;

    issue(0, 0);       cp_commit();
    issue(BK, 1);      cp_commit();

    for (int i = 0; i < nk; i++) {
        const int stg = i % 3;
        cp_wait1();
        __syncthreads();                 // readers of slot (i-1)%3 retired
        if (i + 2 < nk)
            issue((i + 2) * BK, (i + 2) % 3);   // writes slot (i-1)%3
        cp_commit();                     // uniform group numbering

        const uint32_t baseA = sbase + (uint32_t)(stg * TS) * 2u;
        const uint32_t baseB = baseA + (uint32_t)TSZ * 2u;
#pragma unroll
        for (int ks = 0; ks < 2; ks++) {         // 2 x K=16 per 32-k chunk
            const int kr = ks * 16;
            uint32_t a[4][4], b[4][2];
#pragma unroll
            for (int mt = 0; mt < 4; mt++)
                ldsm_x4(a[mt][0], a[mt][1], a[mt][2], a[mt][3],
                        baseA + thrA + (uint32_t)((mt * 16 * STR + kr) * 2));
#pragma unroll
            for (int p = 0; p < 2; p++)
                ldsm_x4(b[2 * p][0], b[2 * p][1], b[2 * p + 1][0], b[2 * p + 1][1],
                        baseB + thrB + (uint32_t)((p * 16 * STR + kr) * 2));
#pragma unroll
            for (int mt = 0; mt < 4; mt++)
#pragma unroll
                for (int nt = 0; nt < 4; nt++)
                    mma_f16(c[mt][nt], a[mt][0], a[mt][1], a[mt][2], a[mt][3],
                            b[nt][0], b[nt][1]);
        }
    }

#pragma unroll
    for (int mt = 0; mt < 4; mt++) {
        const int row = m0 + wm * 64 + mt * 16 + gID;
#pragma unroll
        for (int nt = 0; nt < 4; nt++) {
            const int col = n0 + wn * 32 + nt * 8 + tig * 2;
            if (HALF_OUT) {
                __half* Cp = (__half*)C;
                *reinterpret_cast<__half2*>(Cp + (size_t)row * Ncols + col) =
                    __floats2half2_rn(c[mt][nt][0], c[mt][nt][1]);
                *reinterpret_cast<__half2*>(Cp + (size_t)(row + 8) * Ncols + col) =
                    __floats2half2_rn(c[mt][nt][2], c[mt][nt][3]);
            } else {
                float* Cp = (float*)C;
                *reinterpret_cast<float2*>(Cp + (size_t)row * Ncols + col) =
                    make_float2(c[mt][nt][0], c[mt][nt][1]);
                *reinterpret_cast<float2*>(Cp + (size_t)(row + 8) * Ncols + col) =
                    make_float2(c[mt][nt][2], c[mt][nt][3]);
            }
        }
    }
}

// ---------------------------------------------------------------------------
// fp16 MMA GEMM NN with causal k-limit. C[M,N] = A[M,K] * B[K,N], k < m0+128.
// A (weights) fp16 k-major, frags via ldmatrix; B (V) fp16 n-major, frags via
// ldmatrix.x4.trans. 128x128 tile, 3-stage pipeline, 2 CTA/SM. f32 out.
// ---------------------------------------------------------------------------
__global__ __launch_bounds__(256, 2)
void mma_nn_fp16(const __half* __restrict__ A, const __half* __restrict__ B,
                 float* __restrict__ C, int M, int Ncols, int K)
{
    constexpr int BM = 128, BN = 128, BK = 32;
    constexpr int STRA = BK + 8;                 // 40 halves
    constexpr int STRB = BN + 8;                 // 136 halves = 17 x 16B (odd)
    constexpr int TA = BM * STRA;                // 5120 halves
    constexpr int TB = BK * STRB;                // 4352 halves
    constexpr int TS = TA + TB;                  // 18944 B per stage

    extern __shared__ __half smh[];              // [3][TS]

    const int bx = blockIdx.x, by = blockIdx.y;
    const int m0 = by * BM, n0 = bx * BN;
    const int t    = threadIdx.x;
    const int lane = t & 31, warp = t >> 5;
    const int wm = warp & 1, wn = warp >> 1;
    const int gID = lane >> 2, tig = lane & 3;

    const uint32_t thrA = (uint32_t)(((wm * 64 + ((lane >> 3) & 1) * 8 + (lane & 7)) * STRA
                                      + ((lane >> 4) & 1) * 8) * 2);
    // B (trans): row k = (lane&7) + bit3*8; col n = wn*32 + bit4*8 (+p*16)
    const uint32_t thrBr = (uint32_t)((lane & 7) + ((lane >> 3) & 1) * 8);
    const uint32_t thrBc = (uint32_t)(wn * 32 + ((lane >> 4) & 1) * 8);

    const __half* Ap = A + (size_t)m0 * K;
    const uint32_t sbase = (uint32_t)__cvta_generic_to_shared(smh);

    float c[4][4][4];
#pragma unroll
    for (int i = 0; i < 4; i++)
#pragma unroll
        for (int j = 0; j < 4; j++)
#pragma unroll
            for (int r = 0; r < 4; r++) c[i][j][r] = 0.f;

    auto issue = [&](int k0, int stg) {
        const uint32_t base = sbase + (uint32_t)(stg * TS) * 2u;
#pragma unroll
        for (int l = t; l < 512; l += 256) {     // A: 128 rows x 4 chunks
            const int r  = l >> 2;
            const int cg = l & 3;
            cp_async16(base + (uint32_t)((r * STRA + cg * 8) * 2),
                       Ap + (size_t)r * K + k0 + cg * 8);
        }
#pragma unroll
        for (int l = t; l < 512; l += 256) {     // B: 32 rows(k) x 16 chunks(n)
            const int kk = l >> 4;
            const int ng = l & 15;
            cp_async16(base + (uint32_t)((TA + kk * STRB + ng * 8) * 2),
                       B + (size_t)(k0 + kk) * Ncols + n0 + ng * 8);
        }
    };

    const int kmax = min(K, m0 + BM);   // weights beyond row-tile are exact zeros
    const int nk = kmax / BK;           // >= 4 always

    issue(0, 0);   cp_commit();
    issue(BK, 1);  cp_commit();

    for (int i = 0; i < nk; i++) {
        const int stg = i % 3;
        cp_wait1();
        __syncthreads();
        if (i + 2 < nk)
            issue((i + 2) * BK, (i + 2) % 3);
        cp_commit();

        const uint32_t baseA = sbase + (uint32_t)(stg * TS) * 2u;
        const uint32_t baseB = baseA + (uint32_t)TA * 2u;
#pragma unroll
        for (int ks = 0; ks < 2; ks++) {
            const int kr = ks * 16;
            uint32_t a[4][4], b[4][2];
#pragma unroll
            for (int mt = 0; mt < 4; mt++)
                ldsm_x4(a[mt][0], a[mt][1], a[mt][2], a[mt][3],
                        baseA + thrA + (uint32_t)((mt * 16 * STRA + kr) * 2));
#pragma unroll
            for (int p = 0; p < 2; p++)
                ldsm_x4t(b[2 * p][0], b[2 * p][1], b[2 * p + 1][0], b[2 * p + 1][1],
                         baseB + (uint32_t)((((kr + thrBr)) * STRB + thrBc + p * 16) * 2));
#pragma unroll
            for (int mt = 0; mt < 4; mt++)
#pragma unroll
                for (int nt = 0; nt < 4; nt++)
                    mma_f16(c[mt][nt], a[mt][0], a[mt][1], a[mt][2], a[mt][3],
                            b[nt][0], b[nt][1]);
        }
    }

#pragma unroll
    for (int mt = 0; mt < 4; mt++) {
        const int row = m0 + wm * 64 + mt * 16 + gID;
#pragma unroll
        for (int nt = 0; nt < 4; nt++) {
            const int col = n0 + wn * 32 + nt * 8 + tig * 2;
            *reinterpret_cast<float2*>(C + (size_t)row * Ncols + col) =
                make_float2(c[mt][nt][0], c[mt][nt][1]);
            *reinterpret_cast<float2*>(C + (size_t)(row + 8) * Ncols + col) =
                make_float2(c[mt][nt][2], c[mt][nt][3]);
        }
    }
}

// ---------------------------------------------------------------------------
// Exact JAX *partitionable* threefry2x32 uniform (key = (0, 42)).
// ---------------------------------------------------------------------------
__device__ __forceinline__ float jax_uniform(uint32_t idx)
{
    const uint32_t k0 = 0u, k1 = 42u;
    const uint32_t k2 = 0x1BD11BDAu ^ k0 ^ k1;

    uint32_t x0 = 0u  + k0;
    uint32_t x1 = idx + k1;

#define TF_ROUND(r) { x0 += x1; x1 = __funnelshift_l(x1, x1, (r)); x1 ^= x0; }
    TF_ROUND(13) TF_ROUND(15) TF_ROUND(26) TF_ROUND(6)
    x0 += k1; x1 += k2 + 1u;
    TF_ROUND(17) TF_ROUND(29) TF_ROUND(16) TF_ROUND(24)
    x0 += k2; x1 += k0 + 2u;
    TF_ROUND(13) TF_ROUND(15) TF_ROUND(26) TF_ROUND(6)
    x0 += k0; x1 += k1 + 3u;
    TF_ROUND(17) TF_ROUND(29) TF_ROUND(16) TF_ROUND(24)
    x0 += k1; x1 += k2 + 4u;
    TF_ROUND(13) TF_ROUND(15) TF_ROUND(26) TF_ROUND(6)
    x0 += k2; x1 += k0 + 5u;
#undef TF_ROUND

    uint32_t bits = x0 ^ x1;
    return __uint_as_float((bits >> 9) | 0x3f800000u) - 1.0f;
}

// ---------------------------------------------------------------------------
// Single-pass register-resident softmax (causal, /32) + JAX dropout.
// Reads f32 scores; writes fp16 weights; zero-fills to round_up(len,128).
// ---------------------------------------------------------------------------
__global__ __launch_bounds__(256)
void softmax_dropout_kernel(const float* __restrict__ S, __half* __restrict__ W)
{
    const int i = blockIdx.x;
    const int t = threadIdx.x;
    const int len = i + 1;
    const int wlimit = (len + 127) & ~127;
    const float* row = S + (size_t)i * NT;
    __half* wrow = W + (size_t)i * NT;

    const int warp = t >> 5, lane = t & 31;
    __shared__ float red_m[8], red_s[8];

    const float inv_scale = 0.03125f;  // 1/sqrt(1024)

    float vals[16];
    float lm = -INFINITY;
#pragma unroll
    for (int c = 0; c < 16; c++) {
        const int j = t + 256 * c;
        float x = (j < len) ? row[j] * inv_scale : -INFINITY;
        vals[c] = x;
        lm = fmaxf(lm, x);
    }
#pragma unroll
    for (int o = 16; o; o >>= 1) lm = fmaxf(lm, __shfl_xor_sync(~0u, lm, o));
    if (lane == 0) red_m[warp] = lm;
    __syncthreads();
    float m = red_m[0];
#pragma unroll
    for (int w = 1; w < 8; w++) m = fmaxf(m, red_m[w]);

    float ls = 0.f;
#pragma unroll
    for (int c = 0; c < 16; c++) {
        const int j = t + 256 * c;
        if (j < len) {
            float e = __expf(vals[c] - m);
            vals[c] = e;
            ls += e;
        }
    }
#pragma unroll
    for (int o = 16; o; o >>= 1) ls += __shfl_xor_sync(~0u, ls, o);
    if (lane == 0) red_s[warp] = ls;
    __syncthreads();
    float s = 0.f;
#pragma unroll
    for (int w = 0; w < 8; w++) s += red_s[w];

    const float keep_scale = (1.0f / 0.9f) / s;
    const uint32_t base = (uint32_t)i * (uint32_t)NT;
#pragma unroll
    for (int c = 0; c < 16; c++) {
        const int j = t + 256 * c;
        if (j < wlimit) {
            float w = 0.f;
            if (j < len) {
                float u = jax_uniform(base + (uint32_t)j);
                w = (u < 0.9f) ? vals[c] * keep_scale : 0.f;
            }
            wrow[j] = __float2half_rn(w);
        }
    }
}

// ---------------------------------------------------------------------------
extern "C" void kernel_launch(void* const* d_in, const int* in_sizes, int n_in,
                              void* d_out, int out_size)
{
    const float* x  = (const float*)d_in[0];
    const float* wq = (const float*)d_in[1];
    const float* wk = (const float*)d_in[2];
    const float* wv = (const float*)d_in[3];
    float* out = (float*)d_out;

    __half *q, *k, *v, *w, *xh, *wqh, *wkh, *wvh;
    float *s;
    cudaGetSymbolAddress((void**)&q, g_q);
    cudaGetSymbolAddress((void**)&k, g_k);
    cudaGetSymbolAddress((void**)&v, g_v);
    cudaGetSymbolAddress((void**)&s, g_s);
    cudaGetSymbolAddress((void**)&w, g_w);
    cudaGetSymbolAddress((void**)&xh, g_xh);
    cudaGetSymbolAddress((void**)&wqh, g_wqh);
    cudaGetSymbolAddress((void**)&wkh, g_wkh);
    cudaGetSymbolAddress((void**)&wvh, g_wvh);

    constexpr int sh_nt = 3 * 2 * (128 * 40) * 2;              // 61440 B
    constexpr int sh_nn = 3 * (128 * 40 + 32 * 136) * 2;       // 56832 B

    static bool init_done = false;
    static cudaStream_t s1;
    static cudaEvent_t e_x, e_v;
    if (!init_done) {
        cudaFuncSetAttribute(mma_nt_fp16<false, true>,
                             cudaFuncAttributeMaxDynamicSharedMemorySize, sh_nt);
        cudaFuncSetAttribute(mma_nt_fp16<true, false>,
                             cudaFuncAttributeMaxDynamicSharedMemorySize, sh_nt);
        cudaFuncSetAttribute(mma_nn_fp16,
                             cudaFuncAttributeMaxDynamicSharedMemorySize, sh_nn);
        cudaStreamCreateWithFlags(&s1, cudaStreamNonBlocking);
        cudaEventCreateWithFlags(&e_x, cudaEventDisableTiming);
        cudaEventCreateWithFlags(&e_v, cudaEventDisableTiming);
        init_done = true;
    }

    dim3 blk(256);

    // main stream: convert x, wq, wk to fp16
    tohalf_kernel<<<(NT * DM / 4 + 255) / 256, blk>>>((const float4*)x,  (__half2*)xh,  NT * DM / 4);
    cudaEventRecord(e_x, 0);
    tohalf_kernel<<<(DM * DM / 4 + 255) / 256, blk>>>((const float4*)wq, (__half2*)wqh, DM * DM / 4);
    tohalf_kernel<<<(DM * DM / 4 + 255) / 256, blk>>>((const float4*)wk, (__half2*)wkh, DM * DM / 4);

    // side stream: convert wv, V projection (joins before O-GEMM)
    cudaStreamWaitEvent(s1, e_x, 0);
    tohalf_kernel<<<(DM * DM / 4 + 255) / 256, blk, 0, s1>>>((const float4*)wv, (__half2*)wvh, DM * DM / 4);
    {
        dim3 grid_v(DM / 128, NT / 128, 1);
        mma_nt_fp16<false, true><<<grid_v, blk, sh_nt, s1>>>(
            xh, wvh, wvh, v, v, NT, DM, DM);
    }
    cudaEventRecord(e_v, s1);

    // main stream: QK projections fused via grid.z (fp16 outputs)
    dim3 grid_qk(DM / 128, NT / 128, 2);
    mma_nt_fp16<false, true><<<grid_qk, blk, sh_nt>>>(
        xh, wqh, wkh, q, k, NT, DM, DM);

    // scores = Q @ K^T (skip blocks above diagonal; f32 output)
    dim3 grid_s(NT / 128, NT / 128, 1);
    mma_nt_fp16<true, false><<<grid_s, blk, sh_nt>>>(
        q, k, k, s, s, NT, NT, DM);

    // softmax + dropout (fp16 weights, zero-filled to tile edge)
    softmax_dropout_kernel<<<NT, blk>>>(s, w);

    // join V before the O-GEMM
    cudaStreamWaitEvent(0, e_v, 0);

    // out = weights @ V (causal k-limit per row tile)
    dim3 grid_o(DM / 128, NT / 128);
    mma_nn_fp16<<<grid_o, blk, sh_nn>>>(w, v, out, NT, DM, NT);
}

// round 16
// speedup vs baseline: 1.7514x; 1.0927x over previous
#include <cuda_runtime.h>
#include <cuda_fp16.h>
#include <cstdint>

#define NT 4096
#define DM 1024

// Scratch (static __device__ globals — allocation-free per harness rules)
__device__ __half g_q[(size_t)NT * DM];
__device__ __half g_k[(size_t)NT * DM];
__device__ __half g_v[(size_t)NT * DM];
__device__ float  g_s[(size_t)NT * NT];     // raw scores (f32)
__device__ __half g_w[(size_t)NT * NT];     // dropout-softmax weights (fp16)
__device__ __half g_xh[(size_t)NT * DM];    // fp16 x
__device__ __half g_wqh[(size_t)DM * DM];   // fp16 weights
__device__ __half g_wkh[(size_t)DM * DM];
__device__ __half g_wvh[(size_t)DM * DM];

// ---------------------------------------------------------------------------
// helpers
// ---------------------------------------------------------------------------
__device__ __forceinline__ void mma_f16(float c[4], uint32_t a0, uint32_t a1,
                                        uint32_t a2, uint32_t a3,
                                        uint32_t b0, uint32_t b1)
{
    asm volatile(
        "mma.sync.aligned.m16n8k16.row.col.f32.f16.f16.f32 "
        "{%0,%1,%2,%3}, {%4,%5,%6,%7}, {%8,%9}, {%0,%1,%2,%3};"
        : "+f"(c[0]), "+f"(c[1]), "+f"(c[2]), "+f"(c[3])
        : "r"(a0), "r"(a1), "r"(a2), "r"(a3), "r"(b0), "r"(b1));
}

__device__ __forceinline__ void ldsm_x4(uint32_t& d0, uint32_t& d1,
                                        uint32_t& d2, uint32_t& d3, uint32_t addr)
{
    asm volatile("ldmatrix.sync.aligned.m8n8.x4.shared.b16 {%0,%1,%2,%3}, [%4];"
                 : "=r"(d0), "=r"(d1), "=r"(d2), "=r"(d3) : "r"(addr));
}
__device__ __forceinline__ void ldsm_x4t(uint32_t& d0, uint32_t& d1,
                                         uint32_t& d2, uint32_t& d3, uint32_t addr)
{
    asm volatile("ldmatrix.sync.aligned.m8n8.x4.trans.shared.b16 {%0,%1,%2,%3}, [%4];"
                 : "=r"(d0), "=r"(d1), "=r"(d2), "=r"(d3) : "r"(addr));
}

__device__ __forceinline__ void cp_async16(uint32_t dst_smem, const void* src)
{
    asm volatile("cp.async.cg.shared.global [%0], [%1], 16;\n"
                 :: "r"(dst_smem), "l"(src));
}
__device__ __forceinline__ void cp_commit()
{
    asm volatile("cp.async.commit_group;\n" ::: "memory");
}
__device__ __forceinline__ void cp_wait1()
{
    asm volatile("cp.async.wait_group 1;\n" ::: "memory");
}

// ---------------------------------------------------------------------------
// Fused f32 -> fp16 convert: z=0 -> x (n4x blocks), z=1..3 -> wq/wk/wv (n4w)
// ---------------------------------------------------------------------------
__global__ __launch_bounds__(256)
void tohalf4_kernel(const float4* __restrict__ x,  __half2* __restrict__ xh,  int n4x,
                    const float4* __restrict__ wq, __half2* __restrict__ wqh,
                    const float4* __restrict__ wk, __half2* __restrict__ wkh,
                    const float4* __restrict__ wv, __half2* __restrict__ wvh, int n4w)
{
    const int z = blockIdx.z;
    const float4* in  = (z == 0) ? x : (z == 1) ? wq : (z == 2) ? wk : wv;
    __half2* out      = (z == 0) ? xh : (z == 1) ? wqh : (z == 2) ? wkh : wvh;
    const int n4      = (z == 0) ? n4x : n4w;

    int i = blockIdx.x * blockDim.x + threadIdx.x;
    if (i < n4) {
        float4 v = in[i];
        out[2 * i]     = __floats2half2_rn(v.x, v.y);
        out[2 * i + 1] = __floats2half2_rn(v.z, v.w);
    }
}

// ---------------------------------------------------------------------------
// fp16 MMA GEMM NT. CTA tile 128x128, 8 warps of 64x32 (2m x 4n), BK=64,
// 3-stage cp.async pipeline, one barrier per 64-wide k-chunk, 2 CTA/SM.
// m16n8k16 f16 MMA, fp32 accumulate; fragments via ldmatrix.x4.
// C[M,N] = A[M,K] * B[N,K]^T (A, B fp16 k-major).
// blockIdx.z selects (B, C). CAUSAL: skip blocks above diagonal.
// HALF_OUT: store fp16 (QKV); else f32 (scores).
// ---------------------------------------------------------------------------
template<bool CAUSAL, bool HALF_OUT>
__global__ __launch_bounds__(256, 2)
void mma_nt_fp16(const __half* __restrict__ A,
                 const __half* __restrict__ B0, const __half* __restrict__ B1,
                 void* __restrict__ C0, void* __restrict__ C1,
                 int M, int Ncols, int K)
{
    constexpr int BM = 128, BK = 64;
    constexpr int STR = BK + 8;                 // 72 halves = 9 x 16B (odd): conflict-free
    constexpr int TSZ = BM * STR;               // 9216 halves per operand
    constexpr int TS = 2 * TSZ;                 // 36864 B per stage

    extern __shared__ __half smh[];             // [3][TS]

    const int bx = blockIdx.x, by = blockIdx.y, bz = blockIdx.z;
    if (CAUSAL && bx > by) return;

    const __half* __restrict__ B = (bz == 0) ? B0 : B1;
    void* __restrict__ C         = (bz == 0) ? C0 : C1;

    const int m0 = by * BM, n0 = bx * BM;
    const int t    = threadIdx.x;
    const int lane = t & 31, warp = t >> 5;
    const int wm = warp & 1, wn = warp >> 1;    // 2m x 4n, 64x32 each
    const int gID = lane >> 2, tig = lane & 3;

    // ldmatrix per-thread addresses (bytes):
    // A matrices {(m,k0),(m+8,k0),(m,k8),(m+8,k8)}; B {(n,k0),(n,k8),(n+8,k0),(n+8,k8)}
    const uint32_t thrA = (uint32_t)(((wm * 64 + ((lane >> 3) & 1) * 8 + (lane & 7)) * STR
                                      + ((lane >> 4) & 1) * 8) * 2);
    const uint32_t thrB = (uint32_t)(((wn * 32 + ((lane >> 4) & 1) * 8 + (lane & 7)) * STR
                                      + ((lane >> 3) & 1) * 8) * 2);

    const __half* Ap = A + (size_t)m0 * K;
    const __half* Bp = B + (size_t)n0 * K;
    const uint32_t sbase = (uint32_t)__cvta_generic_to_shared(smh);

    float c[4][4][4];
#pragma unroll
    for (int i = 0; i < 4; i++)
#pragma unroll
        for (int j = 0; j < 4; j++)
#pragma unroll
            for (int r = 0; r < 4; r++) c[i][j][r] = 0.f;

    auto issue = [&](int k0, int stg) {
        const uint32_t base = sbase + (uint32_t)(stg * TS) * 2u;
#pragma unroll
        for (int l = t; l < 1024; l += 256) {   // A: 128 rows x 8 16B-chunks
            const int r  = l >> 3;
            const int cg = l & 7;
            cp_async16(base + (uint32_t)((r * STR + cg * 8) * 2),
                       Ap + (size_t)r * K + k0 + cg * 8);
        }
#pragma unroll
        for (int l = t; l < 1024; l += 256) {   // B: 128 rows x 8 chunks
            const int r  = l >> 3;
            const int cg = l & 7;
            cp_async16(base + (uint32_t)((TSZ + r * STR + cg * 8) * 2),
                       Bp + (size_t)r * K + k0 + cg * 8);
        }
    };

    const int nk = K / BK;                      // 16 for K=1024

    issue(0, 0);       cp_commit();
    issue(BK, 1);      cp_commit();

    for (int i = 0; i < nk; i++) {
        const int stg = i % 3;
        cp_wait1();
        __syncthreads();                 // readers of slot (i-1)%3 retired
        if (i + 2 < nk)
            issue((i + 2) * BK, (i + 2) % 3);   // writes slot (i-1)%3
        cp_commit();                     // uniform group numbering

        const uint32_t baseA = sbase + (uint32_t)(stg * TS) * 2u;
        const uint32_t baseB = baseA + (uint32_t)TSZ * 2u;
#pragma unroll
        for (int ks = 0; ks < 4; ks++) {         // 4 x K=16 per 64-k chunk
            const int kr = ks * 16;
            uint32_t a[4][4], b[4][2];
#pragma unroll
            for (int mt = 0; mt < 4; mt++)
                ldsm_x4(a[mt][0], a[mt][1], a[mt][2], a[mt][3],
                        baseA + thrA + (uint32_t)((mt * 16 * STR + kr) * 2));
#pragma unroll
            for (int p = 0; p < 2; p++)
                ldsm_x4(b[2 * p][0], b[2 * p][1], b[2 * p + 1][0], b[2 * p + 1][1],
                        baseB + thrB + (uint32_t)((p * 16 * STR + kr) * 2));
#pragma unroll
            for (int mt = 0; mt < 4; mt++)
#pragma unroll
                for (int nt = 0; nt < 4; nt++)
                    mma_f16(c[mt][nt], a[mt][0], a[mt][1], a[mt][2], a[mt][3],
                            b[nt][0], b[nt][1]);
        }
    }

#pragma unroll
    for (int mt = 0; mt < 4; mt++) {
        const int row = m0 + wm * 64 + mt * 16 + gID;
#pragma unroll
        for (int nt = 0; nt < 4; nt++) {
            const int col = n0 + wn * 32 + nt * 8 + tig * 2;
            if (HALF_OUT) {
                __half* Cp = (__half*)C;
                *reinterpret_cast<__half2*>(Cp + (size_t)row * Ncols + col) =
                    __floats2half2_rn(c[mt][nt][0], c[mt][nt][1]);
                *reinterpret_cast<__half2*>(Cp + (size_t)(row + 8) * Ncols + col) =
                    __floats2half2_rn(c[mt][nt][2], c[mt][nt][3]);
            } else {
                float* Cp = (float*)C;
                *reinterpret_cast<float2*>(Cp + (size_t)row * Ncols + col) =
                    make_float2(c[mt][nt][0], c[mt][nt][1]);
                *reinterpret_cast<float2*>(Cp + (size_t)(row + 8) * Ncols + col) =
                    make_float2(c[mt][nt][2], c[mt][nt][3]);
            }
        }
    }
}

// ---------------------------------------------------------------------------
// fp16 MMA GEMM NN with causal k-limit. C[M,N] = A[M,K] * B[K,N], k < m0+128.
// BK=64 (nk >= 2). A (weights) fp16 k-major via ldmatrix; B (V) fp16 n-major
// via ldmatrix.x4.trans. 128x128 tile, 3-stage pipeline, 2 CTA/SM. f32 out.
// ---------------------------------------------------------------------------
__global__ __launch_bounds__(256, 2)
void mma_nn_fp16(const __half* __restrict__ A, const __half* __restrict__ B,
                 float* __restrict__ C, int M, int Ncols, int K)
{
    constexpr int BM = 128, BN = 128, BK = 64;
    constexpr int STRA = BK + 8;                 // 72 halves
    constexpr int STRB = BN + 8;                 // 136 halves = 17 x 16B (odd)
    constexpr int TA = BM * STRA;                // 9216 halves
    constexpr int TB = BK * STRB;                // 8704 halves
    constexpr int TS = TA + TB;                  // 35840 B per stage

    extern __shared__ __half smh[];              // [3][TS]

    const int bx = blockIdx.x, by = blockIdx.y;
    const int m0 = by * BM, n0 = bx * BN;
    const int t    = threadIdx.x;
    const int lane = t & 31, warp = t >> 5;
    const int wm = warp & 1, wn = warp >> 1;
    const int gID = lane >> 2, tig = lane & 3;

    const uint32_t thrA = (uint32_t)(((wm * 64 + ((lane >> 3) & 1) * 8 + (lane & 7)) * STRA
                                      + ((lane >> 4) & 1) * 8) * 2);
    // B (trans): row k = (lane&7) + bit3*8; col n = wn*32 + bit4*8 (+p*16)
    const uint32_t thrBr = (uint32_t)((lane & 7) + ((lane >> 3) & 1) * 8);
    const uint32_t thrBc = (uint32_t)(wn * 32 + ((lane >> 4) & 1) * 8);

    const __half* Ap = A + (size_t)m0 * K;
    const uint32_t sbase = (uint32_t)__cvta_generic_to_shared(smh);

    float c[4][4][4];
#pragma unroll
    for (int i = 0; i < 4; i++)
#pragma unroll
        for (int j = 0; j < 4; j++)
#pragma unroll
            for (int r = 0; r < 4; r++) c[i][j][r] = 0.f;

    auto issue = [&](int k0, int stg) {
        const uint32_t base = sbase + (uint32_t)(stg * TS) * 2u;
#pragma unroll
        for (int l = t; l < 1024; l += 256) {    // A: 128 rows x 8 chunks
            const int r  = l >> 3;
            const int cg = l & 7;
            cp_async16(base + (uint32_t)((r * STRA + cg * 8) * 2),
                       Ap + (size_t)r * K + k0 + cg * 8);
        }
#pragma unroll
        for (int l = t; l < 1024; l += 256) {    // B: 64 rows(k) x 16 chunks(n)
            const int kk = l >> 4;
            const int ng = l & 15;
            cp_async16(base + (uint32_t)((TA + kk * STRB + ng * 8) * 2),
                       B + (size_t)(k0 + kk) * Ncols + n0 + ng * 8);
        }
    };

    const int kmax = min(K, m0 + BM);   // weights beyond row-tile are exact zeros
    const int nk = kmax / BK;           // >= 2 always

    issue(0, 0);   cp_commit();
    issue(BK, 1);  cp_commit();

    for (int i = 0; i < nk; i++) {
        const int stg = i % 3;
        cp_wait1();
        __syncthreads();
        if (i + 2 < nk)
            issue((i + 2) * BK, (i + 2) % 3);
        cp_commit();

        const uint32_t baseA = sbase + (uint32_t)(stg * TS) * 2u;
        const uint32_t baseB = baseA + (uint32_t)TA * 2u;
#pragma unroll
        for (int ks = 0; ks < 4; ks++) {
            const int kr = ks * 16;
            uint32_t a[4][4], b[4][2];
#pragma unroll
            for (int mt = 0; mt < 4; mt++)
                ldsm_x4(a[mt][0], a[mt][1], a[mt][2], a[mt][3],
                        baseA + thrA + (uint32_t)((mt * 16 * STRA + kr) * 2));
#pragma unroll
            for (int p = 0; p < 2; p++)
                ldsm_x4t(b[2 * p][0], b[2 * p][1], b[2 * p + 1][0], b[2 * p + 1][1],
                         baseB + (uint32_t)((((kr + thrBr)) * STRB + thrBc + p * 16) * 2));
#pragma unroll
            for (int mt = 0; mt < 4; mt++)
#pragma unroll
                for (int nt = 0; nt < 4; nt++)
                    mma_f16(c[mt][nt], a[mt][0], a[mt][1], a[mt][2], a[mt][3],
                            b[nt][0], b[nt][1]);
        }
    }

#pragma unroll
    for (int mt = 0; mt < 4; mt++) {
        const int row = m0 + wm * 64 + mt * 16 + gID;
#pragma unroll
        for (int nt = 0; nt < 4; nt++) {
            const int col = n0 + wn * 32 + nt * 8 + tig * 2;
            *reinterpret_cast<float2*>(C + (size_t)row * Ncols + col) =
                make_float2(c[mt][nt][0], c[mt][nt][1]);
            *reinterpret_cast<float2*>(C + (size_t)(row + 8) * Ncols + col) =
                make_float2(c[mt][nt][2], c[mt][nt][3]);
        }
    }
}

// ---------------------------------------------------------------------------
// Exact JAX *partitionable* threefry2x32 uniform (key = (0, 42)).
// ---------------------------------------------------------------------------
__device__ __forceinline__ float jax_uniform(uint32_t idx)
{
    const uint32_t k0 = 0u, k1 = 42u;
    const uint32_t k2 = 0x1BD11BDAu ^ k0 ^ k1;

    uint32_t x0 = 0u  + k0;
    uint32_t x1 = idx + k1;

#define TF_ROUND(r) { x0 += x1; x1 = __funnelshift_l(x1, x1, (r)); x1 ^= x0; }
    TF_ROUND(13) TF_ROUND(15) TF_ROUND(26) TF_ROUND(6)
    x0 += k1; x1 += k2 + 1u;
    TF_ROUND(17) TF_ROUND(29) TF_ROUND(16) TF_ROUND(24)
    x0 += k2; x1 += k0 + 2u;
    TF_ROUND(13) TF_ROUND(15) TF_ROUND(26) TF_ROUND(6)
    x0 += k0; x1 += k1 + 3u;
    TF_ROUND(17) TF_ROUND(29) TF_ROUND(16) TF_ROUND(24)
    x0 += k1; x1 += k2 + 4u;
    TF_ROUND(13) TF_ROUND(15) TF_ROUND(26) TF_ROUND(6)
    x0 += k2; x1 += k0 + 5u;
#undef TF_ROUND

    uint32_t bits = x0 ^ x1;
    return __uint_as_float((bits >> 9) | 0x3f800000u) - 1.0f;
}

// ---------------------------------------------------------------------------
// Single-pass register-resident softmax (causal, /32) + JAX dropout.
// Reads f32 scores; writes fp16 weights; zero-fills to round_up(len,128).
// ---------------------------------------------------------------------------
__global__ __launch_bounds__(256)
void softmax_dropout_kernel(const float* __restrict__ S, __half* __restrict__ W)
{
    const int i = blockIdx.x;
    const int t = threadIdx.x;
    const int len = i + 1;
    const int wlimit = (len + 127) & ~127;
    const float* row = S + (size_t)i * NT;
    __half* wrow = W + (size_t)i * NT;

    const int warp = t >> 5, lane = t & 31;
    __shared__ float red_m[8], red_s[8];

    const float inv_scale = 0.03125f;  // 1/sqrt(1024)

    float vals[16];
    float lm = -INFINITY;
#pragma unroll
    for (int c = 0; c < 16; c++) {
        const int j = t + 256 * c;
        float x = (j < len) ? row[j] * inv_scale : -INFINITY;
        vals[c] = x;
        lm = fmaxf(lm, x);
    }
#pragma unroll
    for (int o = 16; o; o >>= 1) lm = fmaxf(lm, __shfl_xor_sync(~0u, lm, o));
    if (lane == 0) red_m[warp] = lm;
    __syncthreads();
    float m = red_m[0];
#pragma unroll
    for (int w = 1; w < 8; w++) m = fmaxf(m, red_m[w]);

    float ls = 0.f;
#pragma unroll
    for (int c = 0; c < 16; c++) {
        const int j = t + 256 * c;
        if (j < len) {
            float e = __expf(vals[c] - m);
            vals[c] = e;
            ls += e;
        }
    }
#pragma unroll
    for (int o = 16; o; o >>= 1) ls += __shfl_xor_sync(~0u, ls, o);
    if (lane == 0) red_s[warp] = ls;
    __syncthreads();
    float s = 0.f;
#pragma unroll
    for (int w = 0; w < 8; w++) s += red_s[w];

    const float keep_scale = (1.0f / 0.9f) / s;
    const uint32_t base = (uint32_t)i * (uint32_t)NT;
#pragma unroll
    for (int c = 0; c < 16; c++) {
        const int j = t + 256 * c;
        if (j < wlimit) {
            float w = 0.f;
            if (j < len) {
                float u = jax_uniform(base + (uint32_t)j);
                w = (u < 0.9f) ? vals[c] * keep_scale : 0.f;
            }
            wrow[j] = __float2half_rn(w);
        }
    }
}

// ---------------------------------------------------------------------------
extern "C" void kernel_launch(void* const* d_in, const int* in_sizes, int n_in,
                              void* d_out, int out_size)
{
    const float* x  = (const float*)d_in[0];
    const float* wq = (const float*)d_in[1];
    const float* wk = (const float*)d_in[2];
    const float* wv = (const float*)d_in[3];
    float* out = (float*)d_out;

    __half *q, *k, *v, *w, *xh, *wqh, *wkh, *wvh;
    float *s;
    cudaGetSymbolAddress((void**)&q, g_q);
    cudaGetSymbolAddress((void**)&k, g_k);
    cudaGetSymbolAddress((void**)&v, g_v);
    cudaGetSymbolAddress((void**)&s, g_s);
    cudaGetSymbolAddress((void**)&w, g_w);
    cudaGetSymbolAddress((void**)&xh, g_xh);
    cudaGetSymbolAddress((void**)&wqh, g_wqh);
    cudaGetSymbolAddress((void**)&wkh, g_wkh);
    cudaGetSymbolAddress((void**)&wvh, g_wvh);

    constexpr int sh_nt = 3 * 2 * (128 * 72) * 2;              // 110592 B
    constexpr int sh_nn = 3 * (128 * 72 + 64 * 136) * 2;       // 107520 B

    static bool init_done = false;
    static cudaStream_t s1;
    static cudaEvent_t e_cvt, e_v;
    if (!init_done) {
        cudaFuncSetAttribute(mma_nt_fp16<false, true>,
                             cudaFuncAttributeMaxDynamicSharedMemorySize, sh_nt);
        cudaFuncSetAttribute(mma_nt_fp16<true, false>,
                             cudaFuncAttributeMaxDynamicSharedMemorySize, sh_nt);
        cudaFuncSetAttribute(mma_nn_fp16,
                             cudaFuncAttributeMaxDynamicSharedMemorySize, sh_nn);
        cudaStreamCreateWithFlags(&s1, cudaStreamNonBlocking);
        cudaEventCreateWithFlags(&e_cvt, cudaEventDisableTiming);
        cudaEventCreateWithFlags(&e_v, cudaEventDisableTiming);
        init_done = true;
    }

    dim3 blk(256);

    // one fused convert launch: x + wq + wk + wv
    const int n4x = NT * DM / 4, n4w = DM * DM / 4;
    dim3 grid_cvt((n4x + 255) / 256, 1, 4);
    tohalf4_kernel<<<grid_cvt, blk>>>((const float4*)x, (__half2*)xh, n4x,
                                      (const float4*)wq, (__half2*)wqh,
                                      (const float4*)wk, (__half2*)wkh,
                                      (const float4*)wv, (__half2*)wvh, n4w);
    cudaEventRecord(e_cvt, 0);

    // side stream: V projection (joins before O-GEMM)
    cudaStreamWaitEvent(s1, e_cvt, 0);
    {
        dim3 grid_v(DM / 128, NT / 128, 1);
        mma_nt_fp16<false, true><<<grid_v, blk, sh_nt, s1>>>(
            xh, wvh, wvh, v, v, NT, DM, DM);
    }
    cudaEventRecord(e_v, s1);

    // main stream: QK projections fused via grid.z (fp16 outputs)
    dim3 grid_qk(DM / 128, NT / 128, 2);
    mma_nt_fp16<false, true><<<grid_qk, blk, sh_nt>>>(
        xh, wqh, wkh, q, k, NT, DM, DM);

    // scores = Q @ K^T (skip blocks above diagonal; f32 output)
    dim3 grid_s(NT / 128, NT / 128, 1);
    mma_nt_fp16<true, false><<<grid_s, blk, sh_nt>>>(
        q, k, k, s, s, NT, NT, DM);

    // softmax + dropout (fp16 weights, zero-filled to tile edge)
    softmax_dropout_kernel<<<NT, blk>>>(s, w);

    // join V before the O-GEMM
    cudaStreamWaitEvent(0, e_v, 0);

    // out = weights @ V (causal k-limit per row tile)
    dim3 grid_o(DM / 128, NT / 128);
    mma_nn_fp16<<<grid_o, blk, sh_nn>>>(w, v, out, NT, DM, NT);
}